// round 13
// baseline (speedup 1.0000x reference)
#include <cuda_runtime.h>

// BoxFilter fused separable 9x9 depthwise conv, fp32 NHWC.
// B=4, H=1080, W=1920, C=16 -> out [4, 1072, 1912, 16].
//
// Round-13 = Round-11 (best: 175.6us) with ONE schedule change inside the
// iteration:  [Ln loads][hphase][Lo loads][vert][bar]
//         ->  [Ln+Lo loads][hphase][vert][bar]
// R11's Lo (L2 ~250cyc) reloads were consumed immediately after issue by the
// vertical phase (fully exposed). Issuing them with the Ln loads gives all 8
// loads the whole horizontal phase to land, and — unlike the failed R12
// rotation — nothing new stays live across the barrier. Tiling (592 blocks
// = 148 SMs x 4), tap scheme, pads, vote, fallback: byte-for-byte R11.

namespace {
constexpr int KS       = 9;
constexpr int Hh       = 1080;
constexpr int Ww       = 1920;
constexpr int Cc       = 16;
constexpr int OH       = 1072;        // H - 8
constexpr int OW       = 1912;        // W - 8
constexpr int EXT_PX   = 60;          // strip width incl. horizontal halo
constexpr int OUT_PX   = 52;          // output pixels per strip
constexpr int NTH      = 240;         // EXT_PX * 4
constexpr int GRID_X   = 37;          // 37*52 >= 1912, last tile overlapped
constexpr int GRID_Y   = 4;
constexpr int ROWS_PB  = OH / GRID_Y;       // 268 output rows per block
constexpr int ITERS    = ROWS_PB / 4;       // 67 four-row iterations
constexpr int IN_ROWS  = ROWS_PB + 8;       // 276 input rows touched
constexpr int IN_ROW_U2   = Ww * Cc / 4;    // 7680 ulonglong2 per input row
constexpr int OUT_ROW_U2  = OW * Cc / 4;    // 7648 ulonglong2 per output row
constexpr int OUT_ROW_U64 = OW * Cc / 2;    // 15296 u64 per output row
constexpr int HTH      = 224;   // 4 rows * 7 groups * 8 u64-lanes
constexpr int SBN      = 272;   // padded ulonglong2 per row buffer (max 267)
}

typedef unsigned long long u64;

__device__ __forceinline__ void fma2(u64 &d, const u64 a, const u64 b) {
    asm("fma.rn.f32x2 %0, %1, %2, %0;" : "+l"(d) : "l"(a), "l"(b));
}
__device__ __forceinline__ void add2(u64 &d, const u64 a) {
    asm("add.rn.f32x2 %0, %0, %1;" : "+l"(d) : "l"(a));
}
__device__ __forceinline__ u64 mul2(const u64 a, const u64 b) {
    u64 r; asm("mul.rn.f32x2 %0, %1, %2;" : "=l"(r) : "l"(a), "l"(b));
    return r;
}
#define NEG1 0xBF800000BF800000ull
__device__ __forceinline__ void sub2(u64 &d, const u64 v) { fma2(d, NEG1, v); }

__device__ __forceinline__ ulonglong2 ldg2(const ulonglong2* p) {
    ulonglong2 v;
    asm volatile("ld.global.v2.u64 {%0,%1}, [%2];"
                 : "=l"(v.x), "=l"(v.y) : "l"(p));
    return v;
}
__device__ __forceinline__ ulonglong2 ldcs2(const ulonglong2* p) {
    ulonglong2 v;
    asm volatile("ld.global.cs.v2.u64 {%0,%1}, [%2];"
                 : "=l"(v.x), "=l"(v.y) : "l"(p));
    return v;
}
__device__ __forceinline__ void stcs1(u64* p, const u64 a) {
    asm volatile("st.global.cs.u64 [%0], %1;" :: "l"(p), "l"(a));
}

// padded smem index (ulonglong2 units) for pixel p, quad qq:
// +4 slots per 8-pixel group (same formula as R7/R11)
__device__ __forceinline__ int sidx(int p, int qq) {
    return p * 4 + qq + ((p >> 3) << 2);
}

// Horizontal: NOUT outputs from (8+NOUT) taps via sliding 9-window sum
// (u64 lanes); lazy tap loads keep at most 9 taps live. NOUT=8 for full
// groups, NOUT=4 for the truncated last group.
template <int NOUT>
__device__ __forceinline__ void hphaseT(const u64* __restrict__ s,
                                        u64* __restrict__ ob,
                                        const int hbase, const u64 scale)
{
    u64 t[9];
    #pragma unroll
    for (int j = 0; j < 9; ++j)
        t[j] = s[hbase + j * 8 + ((j >> 3) << 3)];
    u64 acc = t[0];
    #pragma unroll
    for (int j = 1; j < 9; ++j) add2(acc, t[j]);
    stcs1(ob, mul2(scale, acc));
    #pragma unroll
    for (int o = 1; o < NOUT; ++o) {
        const int j = o + 8;
        const u64 tn = s[hbase + j * 8 + ((j >> 3) << 3)];
        add2(acc, tn);
        sub2(acc, t[o - 1]);
        stcs1(ob + o * 8, mul2(scale, acc));
    }
}

__global__ void __launch_bounds__(NTH, 4)
box_kernel(const float* __restrict__ xg, const float* __restrict__ wyg,
           const float* __restrict__ wxg, float* __restrict__ og)
{
    __shared__ ulonglong2 wy_s[KS * 4];
    __shared__ ulonglong2 wx_s[KS * 4];
    __shared__ ulonglong2 sb[2][4][SBN];     // [buf][row-of-quad][padded col]

    const int tid = threadIdx.x;
    const int q   = tid & 3;
    const int pl  = tid >> 2;                // 0..59 (vertical pixel)

    const int bx = blockIdx.x, by = blockIdx.y, bz = blockIdx.z;
    const int px0 = min(bx * OUT_PX, OW - OUT_PX);   // overlapped last tile
    const int r0  = by * ROWS_PB;

    const ulonglong2* wyv = reinterpret_cast<const ulonglong2*>(wyg);
    const ulonglong2* wxv = reinterpret_cast<const ulonglong2*>(wxg);
    if (tid < KS * 4)                    wy_s[tid]      = wyv[tid];
    else if (tid >= 64 && tid < 64 + 36) wx_s[tid - 64] = wxv[tid - 64];
    __syncthreads();

    // Block-wide bitwise uniformity vote for this thread's channel quad.
    int myuni = 1;
    {
        const ulonglong2 y0 = wy_s[q], x0 = wx_s[q];
        #pragma unroll
        for (int k = 1; k < KS; ++k) {
            const ulonglong2 yk = wy_s[k * 4 + q], xk = wx_s[k * 4 + q];
            myuni &= (yk.x == y0.x) & (yk.y == y0.y)
                   & (xk.x == x0.x) & (xk.y == x0.y);
        }
    }
    const int uniform = __syncthreads_and(myuni);

    const ulonglong2* ib = reinterpret_cast<const ulonglong2*>(xg)
        + (size_t)(bz * Hh + r0) * IN_ROW_U2 + (px0 + pl) * 4 + q;
    const int sst = sidx(pl, q);

    if (uniform) {
        // ------------- fast path: running sums, 4 rows/iter -------------
        const bool hact  = (tid < HTH);      // warps 0..6
        const int  hq    = tid & 7;          // u64 lane within pixel
        const int  hrest = tid >> 3;         // 0..27 when active
        const int  row4  = hrest / 7;
        const int  gx    = hrest - row4 * 7; // 8-px group (gx=6 truncated)
        const int  hbase = 72 * gx + hq;
        const bool full  = (gx < 6);

        u64 scale;
        {
            const ulonglong2 wyq = wy_s[hq >> 1];
            const ulonglong2 wxq = wx_s[hq >> 1];
            const u64 a = (hq & 1) ? wyq.y : wyq.x;
            const u64 c = (hq & 1) ? wxq.y : wxq.x;
            scale = mul2(a, c);
        }

        u64* ob = reinterpret_cast<u64*>(og)
            + (size_t)(bz * OH + r0 + row4) * OUT_ROW_U64
            + (size_t)(px0 + gx * 8) * 8 + hq;

        // Prologue: S = sum rows 0..8; keep rows 0..3 as first leaving rows.
        u64 Sx, Sy;
        ulonglong2 Lo0, Lo1, Lo2, Lo3;
        {
            Lo0 = ldg2(ib);
            Sx = Lo0.x; Sy = Lo0.y;
            Lo1 = ldg2(ib + 1 * IN_ROW_U2); add2(Sx, Lo1.x); add2(Sy, Lo1.y);
            Lo2 = ldg2(ib + 2 * IN_ROW_U2); add2(Sx, Lo2.x); add2(Sy, Lo2.y);
            Lo3 = ldg2(ib + 3 * IN_ROW_U2); add2(Sx, Lo3.x); add2(Sy, Lo3.y);
            #pragma unroll
            for (int k = 4; k < 9; ++k) {
                const ulonglong2 v = ldg2(ib + k * IN_ROW_U2);
                add2(Sx, v.x); add2(Sy, v.y);
            }
        }

        // Iteration 0 (peeled): rows 0..3.
        {
            ulonglong2 Ln0 = ldg2(ib +  9 * IN_ROW_U2);
            ulonglong2 Ln1 = ldg2(ib + 10 * IN_ROW_U2);
            ulonglong2 Ln2 = ldg2(ib + 11 * IN_ROW_U2);
            ulonglong2 Ln3 = ldg2(ib + 12 * IN_ROW_U2);

            { ulonglong2 v; v.x = Sx; v.y = Sy; sb[0][0][sst] = v; }
            add2(Sx, Ln0.x); sub2(Sx, Lo0.x); add2(Sy, Ln0.y); sub2(Sy, Lo0.y);
            { ulonglong2 v; v.x = Sx; v.y = Sy; sb[0][1][sst] = v; }
            add2(Sx, Ln1.x); sub2(Sx, Lo1.x); add2(Sy, Ln1.y); sub2(Sy, Lo1.y);
            { ulonglong2 v; v.x = Sx; v.y = Sy; sb[0][2][sst] = v; }
            add2(Sx, Ln2.x); sub2(Sx, Lo2.x); add2(Sy, Ln2.y); sub2(Sy, Lo2.y);
            { ulonglong2 v; v.x = Sx; v.y = Sy; sb[0][3][sst] = v; }
            add2(Sx, Ln3.x); sub2(Sx, Lo3.x); add2(Sy, Ln3.y); sub2(Sy, Lo3.y);
            __syncthreads();
        }

        for (int i = 1; i < ITERS; ++i) {
            const int r = 4 * i;
            // 1) ALL loads for this iteration up front: Ln (DRAM) and Lo
            //    (L2 re-reads). The horizontal phase below covers both.
            ulonglong2 Ln0 = ldg2(ib + (r +  9) * IN_ROW_U2);
            ulonglong2 Ln1 = ldg2(ib + (r + 10) * IN_ROW_U2);
            ulonglong2 Ln2 = ldg2(ib + (r + 11) * IN_ROW_U2);
            ulonglong2 Ln3 = ldg2(ib + min(r + 12, IN_ROWS - 1) * IN_ROW_U2);
            Lo0 = ldcs2(ib + (r + 0) * IN_ROW_U2);
            Lo1 = ldcs2(ib + (r + 1) * IN_ROW_U2);
            Lo2 = ldcs2(ib + (r + 2) * IN_ROW_U2);
            Lo3 = ldcs2(ib + (r + 3) * IN_ROW_U2);

            // 2) horizontal for iter i-1 (covers all 8 loads)
            if (hact) {
                const u64* s =
                    reinterpret_cast<const u64*>(sb[(i - 1) & 1][row4]);
                if (full) hphaseT<8>(s, ob, hbase, scale);
                else      hphaseT<4>(s, ob, hbase, scale);
                ob += 4 * OUT_ROW_U64;
            }

            // 3) vertical advance: rows r..r+3 into sb[i&1]
            const int buf = i & 1;
            { ulonglong2 v; v.x = Sx; v.y = Sy; sb[buf][0][sst] = v; }
            add2(Sx, Ln0.x); sub2(Sx, Lo0.x); add2(Sy, Ln0.y); sub2(Sy, Lo0.y);
            { ulonglong2 v; v.x = Sx; v.y = Sy; sb[buf][1][sst] = v; }
            add2(Sx, Ln1.x); sub2(Sx, Lo1.x); add2(Sy, Ln1.y); sub2(Sy, Lo1.y);
            { ulonglong2 v; v.x = Sx; v.y = Sy; sb[buf][2][sst] = v; }
            add2(Sx, Ln2.x); sub2(Sx, Lo2.x); add2(Sy, Ln2.y); sub2(Sy, Lo2.y);
            { ulonglong2 v; v.x = Sx; v.y = Sy; sb[buf][3][sst] = v; }
            add2(Sx, Ln3.x); sub2(Sx, Lo3.x); add2(Sy, Ln3.y); sub2(Sy, Lo3.y);

            __syncthreads();
        }

        // Epilogue: horizontal for the last iteration.
        if (hact) {
            const u64* s =
                reinterpret_cast<const u64*>(sb[(ITERS - 1) & 1][row4]);
            if (full) hphaseT<8>(s, ob, hbase, scale);
            else      hphaseT<4>(s, ob, hbase, scale);
        }
    } else {
        // ------------- fallback: full 9-tap FMA (any weights) -------------
        const bool emit = (pl < OUT_PX);
        ulonglong2* op = reinterpret_cast<ulonglong2*>(og)
            + (size_t)(bz * OH + r0) * OUT_ROW_U2 + (px0 + pl) * 4 + q;

        ulonglong2 win[8], cur, nxt;
        const ulonglong2* ip = ib;
        #pragma unroll
        for (int k = 0; k < 8; ++k) { win[k] = *ip; ip += IN_ROW_U2; }
        cur = *ip; ip += IN_ROW_U2;
        nxt = *ip; ip += IN_ROW_U2;

        for (int i = 0; i < ROWS_PB / 2; ++i) {
            ulonglong2 p0 = cur, p1 = cur;
            if (2 * i + 10 < IN_ROWS) p0 = ip[0];
            if (2 * i + 11 < IN_ROWS) p1 = ip[IN_ROW_U2];
            ip += 2 * IN_ROW_U2;

            u64 a0x = 0, a0y = 0, a1x = 0, a1y = 0;
            #pragma unroll
            for (int k = 0; k < KS; ++k) {
                const ulonglong2 w   = wy_s[k * 4 + q];
                const ulonglong2 r0v = (k < 8) ? win[k] : cur;
                const ulonglong2 r1v = (k < 7) ? win[k + 1] : ((k == 7) ? cur : nxt);
                fma2(a0x, w.x, r0v.x); fma2(a0y, w.y, r0v.y);
                fma2(a1x, w.x, r1v.x); fma2(a1y, w.y, r1v.y);
            }
            const int buf = i & 1;
            { ulonglong2 v; v.x = a0x; v.y = a0y; sb[buf][0][sst] = v; }
            { ulonglong2 v; v.x = a1x; v.y = a1y; sb[buf][1][sst] = v; }

            #pragma unroll
            for (int k = 0; k < 6; ++k) win[k] = win[k + 2];
            win[6] = cur; win[7] = nxt;
            cur = p0; nxt = p1;

            __syncthreads();

            if (emit) {
                u64 o0x = 0, o0y = 0, o1x = 0, o1y = 0;
                #pragma unroll
                for (int j = 0; j < KS; ++j) {
                    const ulonglong2 w  = wx_s[j * 4 + q];
                    const ulonglong2 t0 = sb[buf][0][sidx(pl + j, q)];
                    const ulonglong2 t1 = sb[buf][1][sidx(pl + j, q)];
                    fma2(o0x, w.x, t0.x); fma2(o0y, w.y, t0.y);
                    fma2(o1x, w.x, t1.x); fma2(o1y, w.y, t1.y);
                }
                ulonglong2 v0; v0.x = o0x; v0.y = o0y;
                ulonglong2 v1; v1.x = o1x; v1.y = o1y;
                op[0]          = v0;
                op[OUT_ROW_U2] = v1;
            }
            op += 2 * OUT_ROW_U2;
            __syncthreads();
        }
    }
}

extern "C" void kernel_launch(void* const* d_in, const int* in_sizes, int n_in,
                              void* d_out, int out_size)
{
    const float* x  = (const float*)d_in[0];
    const float* wy = (const float*)d_in[1];
    const float* wx = (const float*)d_in[2];
    float* out = (float*)d_out;

    dim3 grid(GRID_X, GRID_Y, 4);
    dim3 block(NTH);
    box_kernel<<<grid, block>>>(x, wy, wx, out);
}

// round 14
// speedup vs baseline: 1.2086x; 1.2086x over previous
#include <cuda_runtime.h>

// BoxFilter fused separable 9x9 depthwise conv, fp32 NHWC.
// B=4, H=1080, W=1920, C=16 -> out [4, 1072, 1912, 16].
//
// FINAL = Round-11 (best measured: 175.6us, DRAM 74.6%, ideal 1.03GB HBM
// traffic, 592 perfectly balanced blocks = 148 SMs x 4).
// Structure: fused separable filter; uniform-weight fast path (block-wide
// bitwise vote) computes vertical 9-row running sums (S += new - old, new
// rows from DRAM, leaving rows re-read from L2 with .cs), exchanges 4 rows
// per barrier through padded conflict-free smem, horizontal 9-window sliding
// sums produce 8 outputs per thread (2.0 LDS.64/output), one fused
// wy0*wx0 scale, streaming stores. Schedule [Ln loads -> hphase -> Lo loads
// -> vert -> bar] is the empirically-proven optimum: five alternative
// schedules (R8/R9/R10/R12/R13) all regressed under the 64-reg/4-block
// budget. Generic 9-tap FMA fallback handles arbitrary weights.

namespace {
constexpr int KS       = 9;
constexpr int Hh       = 1080;
constexpr int Ww       = 1920;
constexpr int Cc       = 16;
constexpr int OH       = 1072;        // H - 8
constexpr int OW       = 1912;        // W - 8
constexpr int EXT_PX   = 60;          // strip width incl. horizontal halo
constexpr int OUT_PX   = 52;          // output pixels per strip
constexpr int NTH      = 240;         // EXT_PX * 4
constexpr int GRID_X   = 37;          // 37*52 >= 1912, last tile overlapped
constexpr int GRID_Y   = 4;
constexpr int ROWS_PB  = OH / GRID_Y;       // 268 output rows per block
constexpr int ITERS    = ROWS_PB / 4;       // 67 four-row iterations
constexpr int IN_ROWS  = ROWS_PB + 8;       // 276 input rows touched
constexpr int IN_ROW_U2   = Ww * Cc / 4;    // 7680 ulonglong2 per input row
constexpr int OUT_ROW_U2  = OW * Cc / 4;    // 7648 ulonglong2 per output row
constexpr int OUT_ROW_U64 = OW * Cc / 2;    // 15296 u64 per output row
constexpr int HTH      = 224;   // 4 rows * 7 groups * 8 u64-lanes
constexpr int SBN      = 272;   // padded ulonglong2 per row buffer (max 267)
}

typedef unsigned long long u64;

__device__ __forceinline__ void fma2(u64 &d, const u64 a, const u64 b) {
    asm("fma.rn.f32x2 %0, %1, %2, %0;" : "+l"(d) : "l"(a), "l"(b));
}
__device__ __forceinline__ void add2(u64 &d, const u64 a) {
    asm("add.rn.f32x2 %0, %0, %1;" : "+l"(d) : "l"(a));
}
__device__ __forceinline__ u64 mul2(const u64 a, const u64 b) {
    u64 r; asm("mul.rn.f32x2 %0, %1, %2;" : "=l"(r) : "l"(a), "l"(b));
    return r;
}
#define NEG1 0xBF800000BF800000ull
__device__ __forceinline__ void sub2(u64 &d, const u64 v) { fma2(d, NEG1, v); }

__device__ __forceinline__ ulonglong2 ldg2(const ulonglong2* p) {
    ulonglong2 v;
    asm volatile("ld.global.v2.u64 {%0,%1}, [%2];"
                 : "=l"(v.x), "=l"(v.y) : "l"(p));
    return v;
}
__device__ __forceinline__ ulonglong2 ldcs2(const ulonglong2* p) {
    ulonglong2 v;
    asm volatile("ld.global.cs.v2.u64 {%0,%1}, [%2];"
                 : "=l"(v.x), "=l"(v.y) : "l"(p));
    return v;
}
__device__ __forceinline__ void stcs1(u64* p, const u64 a) {
    asm volatile("st.global.cs.u64 [%0], %1;" :: "l"(p), "l"(a));
}

// padded smem index (ulonglong2 units) for pixel p, quad qq:
// +4 slots per 8-pixel group
__device__ __forceinline__ int sidx(int p, int qq) {
    return p * 4 + qq + ((p >> 3) << 2);
}

// Horizontal: NOUT outputs from (8+NOUT) taps via sliding 9-window sum
// (u64 lanes); lazy tap loads keep at most 9 taps live. NOUT=8 for full
// groups, NOUT=4 for the truncated last group.
template <int NOUT>
__device__ __forceinline__ void hphaseT(const u64* __restrict__ s,
                                        u64* __restrict__ ob,
                                        const int hbase, const u64 scale)
{
    u64 t[9];
    #pragma unroll
    for (int j = 0; j < 9; ++j)
        t[j] = s[hbase + j * 8 + ((j >> 3) << 3)];
    u64 acc = t[0];
    #pragma unroll
    for (int j = 1; j < 9; ++j) add2(acc, t[j]);
    stcs1(ob, mul2(scale, acc));
    #pragma unroll
    for (int o = 1; o < NOUT; ++o) {
        const int j = o + 8;
        const u64 tn = s[hbase + j * 8 + ((j >> 3) << 3)];
        add2(acc, tn);
        sub2(acc, t[o - 1]);
        stcs1(ob + o * 8, mul2(scale, acc));
    }
}

__global__ void __launch_bounds__(NTH, 4)
box_kernel(const float* __restrict__ xg, const float* __restrict__ wyg,
           const float* __restrict__ wxg, float* __restrict__ og)
{
    __shared__ ulonglong2 wy_s[KS * 4];
    __shared__ ulonglong2 wx_s[KS * 4];
    __shared__ ulonglong2 sb[2][4][SBN];     // [buf][row-of-quad][padded col]

    const int tid = threadIdx.x;
    const int q   = tid & 3;
    const int pl  = tid >> 2;                // 0..59 (vertical pixel)

    const int bx = blockIdx.x, by = blockIdx.y, bz = blockIdx.z;
    const int px0 = min(bx * OUT_PX, OW - OUT_PX);   // overlapped last tile
    const int r0  = by * ROWS_PB;

    const ulonglong2* wyv = reinterpret_cast<const ulonglong2*>(wyg);
    const ulonglong2* wxv = reinterpret_cast<const ulonglong2*>(wxg);
    if (tid < KS * 4)                    wy_s[tid]      = wyv[tid];
    else if (tid >= 64 && tid < 64 + 36) wx_s[tid - 64] = wxv[tid - 64];
    __syncthreads();

    // Block-wide bitwise uniformity vote for this thread's channel quad.
    int myuni = 1;
    {
        const ulonglong2 y0 = wy_s[q], x0 = wx_s[q];
        #pragma unroll
        for (int k = 1; k < KS; ++k) {
            const ulonglong2 yk = wy_s[k * 4 + q], xk = wx_s[k * 4 + q];
            myuni &= (yk.x == y0.x) & (yk.y == y0.y)
                   & (xk.x == x0.x) & (xk.y == x0.y);
        }
    }
    const int uniform = __syncthreads_and(myuni);

    const ulonglong2* ib = reinterpret_cast<const ulonglong2*>(xg)
        + (size_t)(bz * Hh + r0) * IN_ROW_U2 + (px0 + pl) * 4 + q;
    const int sst = sidx(pl, q);

    if (uniform) {
        // ------------- fast path: running sums, 4 rows/iter -------------
        const bool hact  = (tid < HTH);      // warps 0..6
        const int  hq    = tid & 7;          // u64 lane within pixel
        const int  hrest = tid >> 3;         // 0..27 when active
        const int  row4  = hrest / 7;
        const int  gx    = hrest - row4 * 7; // 8-px group (gx=6 truncated)
        const int  hbase = 72 * gx + hq;
        const bool full  = (gx < 6);

        u64 scale;
        {
            const ulonglong2 wyq = wy_s[hq >> 1];
            const ulonglong2 wxq = wx_s[hq >> 1];
            const u64 a = (hq & 1) ? wyq.y : wyq.x;
            const u64 c = (hq & 1) ? wxq.y : wxq.x;
            scale = mul2(a, c);
        }

        u64* ob = reinterpret_cast<u64*>(og)
            + (size_t)(bz * OH + r0 + row4) * OUT_ROW_U64
            + (size_t)(px0 + gx * 8) * 8 + hq;

        // Prologue: S = sum rows 0..8; keep rows 0..3 as first leaving rows.
        u64 Sx, Sy;
        ulonglong2 Lo0, Lo1, Lo2, Lo3;
        {
            Lo0 = ldg2(ib);
            Sx = Lo0.x; Sy = Lo0.y;
            Lo1 = ldg2(ib + 1 * IN_ROW_U2); add2(Sx, Lo1.x); add2(Sy, Lo1.y);
            Lo2 = ldg2(ib + 2 * IN_ROW_U2); add2(Sx, Lo2.x); add2(Sy, Lo2.y);
            Lo3 = ldg2(ib + 3 * IN_ROW_U2); add2(Sx, Lo3.x); add2(Sy, Lo3.y);
            #pragma unroll
            for (int k = 4; k < 9; ++k) {
                const ulonglong2 v = ldg2(ib + k * IN_ROW_U2);
                add2(Sx, v.x); add2(Sy, v.y);
            }
        }

        // Iteration 0 (peeled): rows 0..3.
        {
            ulonglong2 Ln0 = ldg2(ib +  9 * IN_ROW_U2);
            ulonglong2 Ln1 = ldg2(ib + 10 * IN_ROW_U2);
            ulonglong2 Ln2 = ldg2(ib + 11 * IN_ROW_U2);
            ulonglong2 Ln3 = ldg2(ib + 12 * IN_ROW_U2);

            { ulonglong2 v; v.x = Sx; v.y = Sy; sb[0][0][sst] = v; }
            add2(Sx, Ln0.x); sub2(Sx, Lo0.x); add2(Sy, Ln0.y); sub2(Sy, Lo0.y);
            { ulonglong2 v; v.x = Sx; v.y = Sy; sb[0][1][sst] = v; }
            add2(Sx, Ln1.x); sub2(Sx, Lo1.x); add2(Sy, Ln1.y); sub2(Sy, Lo1.y);
            { ulonglong2 v; v.x = Sx; v.y = Sy; sb[0][2][sst] = v; }
            add2(Sx, Ln2.x); sub2(Sx, Lo2.x); add2(Sy, Ln2.y); sub2(Sy, Lo2.y);
            { ulonglong2 v; v.x = Sx; v.y = Sy; sb[0][3][sst] = v; }
            add2(Sx, Ln3.x); sub2(Sx, Lo3.x); add2(Sy, Ln3.y); sub2(Sy, Lo3.y);
            __syncthreads();
        }

        for (int i = 1; i < ITERS; ++i) {
            const int r = 4 * i;
            // 1) DRAM-critical new-row loads first
            ulonglong2 Ln0 = ldg2(ib + (r +  9) * IN_ROW_U2);
            ulonglong2 Ln1 = ldg2(ib + (r + 10) * IN_ROW_U2);
            ulonglong2 Ln2 = ldg2(ib + (r + 11) * IN_ROW_U2);
            ulonglong2 Ln3 = ldg2(ib + min(r + 12, IN_ROWS - 1) * IN_ROW_U2);

            // 2) horizontal for iter i-1 (covers load latency)
            if (hact) {
                const u64* s =
                    reinterpret_cast<const u64*>(sb[(i - 1) & 1][row4]);
                if (full) hphaseT<8>(s, ob, hbase, scale);
                else      hphaseT<4>(s, ob, hbase, scale);
                ob += 4 * OUT_ROW_U64;
            }

            // 3) leaving-row reloads (L2 hits)
            Lo0 = ldcs2(ib + (r + 0) * IN_ROW_U2);
            Lo1 = ldcs2(ib + (r + 1) * IN_ROW_U2);
            Lo2 = ldcs2(ib + (r + 2) * IN_ROW_U2);
            Lo3 = ldcs2(ib + (r + 3) * IN_ROW_U2);

            // 4) vertical advance: rows r..r+3 into sb[i&1]
            const int buf = i & 1;
            { ulonglong2 v; v.x = Sx; v.y = Sy; sb[buf][0][sst] = v; }
            add2(Sx, Ln0.x); sub2(Sx, Lo0.x); add2(Sy, Ln0.y); sub2(Sy, Lo0.y);
            { ulonglong2 v; v.x = Sx; v.y = Sy; sb[buf][1][sst] = v; }
            add2(Sx, Ln1.x); sub2(Sx, Lo1.x); add2(Sy, Ln1.y); sub2(Sy, Lo1.y);
            { ulonglong2 v; v.x = Sx; v.y = Sy; sb[buf][2][sst] = v; }
            add2(Sx, Ln2.x); sub2(Sx, Lo2.x); add2(Sy, Ln2.y); sub2(Sy, Lo2.y);
            { ulonglong2 v; v.x = Sx; v.y = Sy; sb[buf][3][sst] = v; }
            add2(Sx, Ln3.x); sub2(Sx, Lo3.x); add2(Sy, Ln3.y); sub2(Sy, Lo3.y);

            __syncthreads();
        }

        // Epilogue: horizontal for the last iteration.
        if (hact) {
            const u64* s =
                reinterpret_cast<const u64*>(sb[(ITERS - 1) & 1][row4]);
            if (full) hphaseT<8>(s, ob, hbase, scale);
            else      hphaseT<4>(s, ob, hbase, scale);
        }
    } else {
        // ------------- fallback: full 9-tap FMA (any weights) -------------
        const bool emit = (pl < OUT_PX);
        ulonglong2* op = reinterpret_cast<ulonglong2*>(og)
            + (size_t)(bz * OH + r0) * OUT_ROW_U2 + (px0 + pl) * 4 + q;

        ulonglong2 win[8], cur, nxt;
        const ulonglong2* ip = ib;
        #pragma unroll
        for (int k = 0; k < 8; ++k) { win[k] = *ip; ip += IN_ROW_U2; }
        cur = *ip; ip += IN_ROW_U2;
        nxt = *ip; ip += IN_ROW_U2;

        for (int i = 0; i < ROWS_PB / 2; ++i) {
            ulonglong2 p0 = cur, p1 = cur;
            if (2 * i + 10 < IN_ROWS) p0 = ip[0];
            if (2 * i + 11 < IN_ROWS) p1 = ip[IN_ROW_U2];
            ip += 2 * IN_ROW_U2;

            u64 a0x = 0, a0y = 0, a1x = 0, a1y = 0;
            #pragma unroll
            for (int k = 0; k < KS; ++k) {
                const ulonglong2 w   = wy_s[k * 4 + q];
                const ulonglong2 r0v = (k < 8) ? win[k] : cur;
                const ulonglong2 r1v = (k < 7) ? win[k + 1] : ((k == 7) ? cur : nxt);
                fma2(a0x, w.x, r0v.x); fma2(a0y, w.y, r0v.y);
                fma2(a1x, w.x, r1v.x); fma2(a1y, w.y, r1v.y);
            }
            const int buf = i & 1;
            { ulonglong2 v; v.x = a0x; v.y = a0y; sb[buf][0][sst] = v; }
            { ulonglong2 v; v.x = a1x; v.y = a1y; sb[buf][1][sst] = v; }

            #pragma unroll
            for (int k = 0; k < 6; ++k) win[k] = win[k + 2];
            win[6] = cur; win[7] = nxt;
            cur = p0; nxt = p1;

            __syncthreads();

            if (emit) {
                u64 o0x = 0, o0y = 0, o1x = 0, o1y = 0;
                #pragma unroll
                for (int j = 0; j < KS; ++j) {
                    const ulonglong2 w  = wx_s[j * 4 + q];
                    const ulonglong2 t0 = sb[buf][0][sidx(pl + j, q)];
                    const ulonglong2 t1 = sb[buf][1][sidx(pl + j, q)];
                    fma2(o0x, w.x, t0.x); fma2(o0y, w.y, t0.y);
                    fma2(o1x, w.x, t1.x); fma2(o1y, w.y, t1.y);
                }
                ulonglong2 v0; v0.x = o0x; v0.y = o0y;
                ulonglong2 v1; v1.x = o1x; v1.y = o1y;
                op[0]          = v0;
                op[OUT_ROW_U2] = v1;
            }
            op += 2 * OUT_ROW_U2;
            __syncthreads();
        }
    }
}

extern "C" void kernel_launch(void* const* d_in, const int* in_sizes, int n_in,
                              void* d_out, int out_size)
{
    const float* x  = (const float*)d_in[0];
    const float* wy = (const float*)d_in[1];
    const float* wx = (const float*)d_in[2];
    float* out = (float*)d_out;

    dim3 grid(GRID_X, GRID_Y, 4);
    dim3 block(NTH);
    box_kernel<<<grid, block>>>(x, wy, wx, out);
}